// round 5
// baseline (speedup 1.0000x reference)
#include <cuda_runtime.h>

// Problem dims
#define N_  20000
#define K_  20
#define T_  50
#define D_  200
#define T2  25            // t-pairs (f32x2 packing over fastest axis)
#define NT  32            // n rows per block
#define DC  8             // d chunk size
#define NNN 4             // n rows per compute thread-tile
#define BLK 512           // 16 warps
#define HALF 256          // threads per d-half
#define NCHUNK (D_/DC)    // 25 chunks: half0 -> 0..12, half1 -> 13..24
#define EPSF 1e-8f

typedef unsigned long long u64;

// Precomputed sigmoid(phi), filled by kernel 1, read by kernel 2.
__device__ float g_phiprob[K_ * D_ * T_];

__device__ __forceinline__ u64 ffma2(u64 a, u64 b, u64 c) {
    u64 d;
    asm("fma.rn.f32x2 %0, %1, %2, %3;" : "=l"(d) : "l"(a), "l"(b), "l"(c));
    return d;
}

__device__ __forceinline__ void half_bar(int bar_id) {
    asm volatile("bar.sync %0, %1;" :: "r"(bar_id), "r"(HALF) : "memory");
}

__global__ void phi_sigmoid_kernel(const float* __restrict__ phi,
                                   float* __restrict__ out_phi) {
    int i = blockIdx.x * blockDim.x + threadIdx.x;
    if (i < K_ * D_ * T_) {
        float p = __fdividef(1.f, 1.f + __expf(-phi[i]));
        out_phi[i]   = p;
        g_phiprob[i] = p;
    }
}

__global__ __launch_bounds__(BLK, 1) void main_kernel(
    const float* __restrict__ lambda_,
    float* __restrict__ pi_out,
    float* __restrict__ theta_out)
{
    extern __shared__ float2 smem[];
    float2* theta_s = smem;                      // [K_][NT][T2]       = 128000 B
    float2* phi_all = smem + K_ * NT * T2;       // 2 x [K_][DC][T2]   =  32000 B

    const int tid   = threadIdx.x;
    const int nbase = blockIdx.x * NT;
    const float2* lam2 = (const float2*)lambda_;
    float2*       th2  = (float2*)theta_out;
    float2*       pi2  = (float2*)pi_out;
    const float2* pp2  = (const float2*)g_phiprob;

    // ---------------- Stage 1: softmax over K for this block's 32 n's ----------------
    for (int cell = tid; cell < NT * T2; cell += BLK) {
        int t2 = cell % T2;
        int n  = cell / T2;
        size_t base = (size_t)(nbase + n) * K_ * T2 + t2;

        float2 v[K_];
        #pragma unroll
        for (int k = 0; k < K_; k++) v[k] = lam2[base + (size_t)k * T2];

        float mx = v[0].x, my = v[0].y;
        #pragma unroll
        for (int k = 1; k < K_; k++) { mx = fmaxf(mx, v[k].x); my = fmaxf(my, v[k].y); }

        float sx = 0.f, sy = 0.f;
        #pragma unroll
        for (int k = 0; k < K_; k++) {
            v[k].x = __expf(v[k].x - mx);
            v[k].y = __expf(v[k].y - my);
            sx += v[k].x; sy += v[k].y;
        }
        float ix = __fdividef(1.f, sx), iy = __fdividef(1.f, sy);

        #pragma unroll
        for (int k = 0; k < K_; k++) {
            float2 th; th.x = v[k].x * ix; th.y = v[k].y * iy;
            theta_s[(k * NT + n) * T2 + t2] = th;       // [k][n][t2]
            th2[base + (size_t)k * T2] = th;            // coalesced global write
        }
    }
    __syncthreads();

    // ---------------- Stage 2: two independent 256-thread halves ----------------
    // Warp = one n-group; lane = t2 (lanes 25..31 idle in compute, active in staging).
    const int wid  = tid >> 5;          // 0..15
    const int lane = tid & 31;
    const int halfsel = wid >> 3;       // 0: warps 0-7, 1: warps 8-15
    const int ngrp    = wid & 7;
    const int n0      = ngrp * NNN;
    const int ltid    = tid & (HALF - 1);

    float2* phi_s = phi_all + halfsel * (K_ * DC * T2);
    const int bar = 1 + halfsel;
    const int c_lo = halfsel ? 13 : 0;
    const int c_hi = halfsel ? NCHUNK : 13;

    for (int chunk = c_lo; chunk < c_hi; chunk++) {
        const int d0 = chunk * DC;

        // Stage phi chunk [K_][DC][T2] = 4000 float2 (this half's 256 threads)
        {
            const float2* src = pp2 + (size_t)d0 * T2;
            #pragma unroll 1
            for (int i = ltid; i < K_ * DC * T2; i += HALF) {
                int k   = i / (DC * T2);
                int rem = i - k * (DC * T2);
                phi_s[i] = src[(size_t)k * (D_ * T2) + rem];
            }
        }
        half_bar(bar);

        if (lane < T2) {
            const int t2c = lane;
            u64 acc[NNN][DC];
            #pragma unroll
            for (int i = 0; i < NNN; i++)
                #pragma unroll
                for (int d = 0; d < DC; d++) acc[i][d] = 0ull;

            #pragma unroll
            for (int k = 0; k < K_; k++) {
                u64 th[NNN], ph[DC];
                #pragma unroll
                for (int i = 0; i < NNN; i++)
                    th[i] = *(const u64*)&theta_s[(k * NT + n0 + i) * T2 + t2c];
                #pragma unroll
                for (int d = 0; d < DC; d++)
                    ph[d] = *(const u64*)&phi_s[(k * DC + d) * T2 + t2c];
                #pragma unroll
                for (int i = 0; i < NNN; i++)
                    #pragma unroll
                    for (int d = 0; d < DC; d++)
                        acc[i][d] = ffma2(th[i], ph[d], acc[i][d]);
            }

            float2* pi_base = pi2 + ((size_t)(nbase + n0) * D_ + d0) * T2 + t2c;
            #pragma unroll
            for (int i = 0; i < NNN; i++) {
                #pragma unroll
                for (int d = 0; d < DC; d++) {
                    float2 f;
                    asm("mov.b64 {%0, %1}, %2;" : "=f"(f.x), "=f"(f.y) : "l"(acc[i][d]));
                    f.x = fminf(fmaxf(f.x, EPSF), 1.f - EPSF);
                    f.y = fminf(fmaxf(f.y, EPSF), 1.f - EPSF);
                    pi_base[((size_t)i * D_ + d) * T2] = f;
                }
            }
        }
        half_bar(bar);   // protect phi_s before next chunk's staging
    }
}

extern "C" void kernel_launch(void* const* d_in, const int* in_sizes, int n_in,
                              void* d_out, int out_size) {
    const float* lambda_ = (const float*)d_in[0];   // [N, K, T]
    const float* phi     = (const float*)d_in[1];   // [K, D, T]

    float* out         = (float*)d_out;
    float* pi_out      = out;                                // 200,000,000
    float* theta_out   = out + (size_t)N_ * D_ * T_;         //  20,000,000
    float* phiprob_out = theta_out + (size_t)N_ * K_ * T_;   //     200,000

    phi_sigmoid_kernel<<<(K_ * D_ * T_ + 255) / 256, 256>>>(phi, phiprob_out);

    size_t smem_bytes = sizeof(float2) *
        (size_t)(K_ * NT * T2 + 2 * K_ * DC * T2);           // 160000 B
    cudaFuncSetAttribute(main_kernel, cudaFuncAttributeMaxDynamicSharedMemorySize,
                         (int)smem_bytes);
    main_kernel<<<N_ / NT, BLK, smem_bytes>>>(lambda_, pi_out, theta_out);
}

// round 6
// speedup vs baseline: 1.1888x; 1.1888x over previous
#include <cuda_runtime.h>

// Problem dims
#define N_  20000
#define K_  20
#define T_  50
#define D_  200
#define T2  25            // t-pairs (f32x2 over fastest axis)
#define NT  32            // n rows per block
#define DC  8             // d chunk size
#define NNN 4             // n rows per warp tile
#define PHIPAD 32         // phi_s row stride in float2 (256B, 128B-aligned)
#define BLK 512           // 16 warps
#define HALF 256          // threads per d-half
#define NCHUNK (D_/DC)    // 25 chunks: half0 -> 0..12, half1 -> 13..24
#define EPSF 1e-8f

typedef unsigned long long u64;

// Precomputed sigmoid(phi), filled by kernel 1, read by kernel 2.
// +4 floats pad: staging may read slightly past the logical end.
__device__ float g_phiprob[K_ * D_ * T_ + 4];

__device__ __forceinline__ u64 ffma2(u64 a, u64 b, u64 c) {
    u64 d;
    asm("fma.rn.f32x2 %0, %1, %2, %3;" : "=l"(d) : "l"(a), "l"(b), "l"(c));
    return d;
}

__device__ __forceinline__ void half_bar(int bar_id) {
    asm volatile("bar.sync %0, %1;" :: "r"(bar_id), "r"(HALF) : "memory");
}

__global__ void phi_sigmoid_kernel(const float* __restrict__ phi,
                                   float* __restrict__ out_phi) {
    int i = blockIdx.x * blockDim.x + threadIdx.x;
    if (i < K_ * D_ * T_) {
        float p = __fdividef(1.f, 1.f + __expf(-phi[i]));
        out_phi[i]   = p;
        g_phiprob[i] = p;
    }
}

__global__ __launch_bounds__(BLK, 1) void main_kernel(
    const float* __restrict__ lambda_,
    float* __restrict__ pi_out,
    float* __restrict__ theta_out)
{
    extern __shared__ float2 smem[];
    float2* theta_s = smem;                      // [K_][NT][T2]          = 128000 B
    float2* phi_all = smem + K_ * NT * T2;       // 2 x [K_][DC][PHIPAD]  =  81920 B

    const int tid   = threadIdx.x;
    const int nbase = blockIdx.x * NT;
    const float2* lam2 = (const float2*)lambda_;
    float2*       th2  = (float2*)theta_out;
    float2*       pi2  = (float2*)pi_out;
    const float2* pp2  = (const float2*)g_phiprob;

    // ---------------- Stage 1: softmax over K for this block's 32 n's ----------------
    if (tid < NT * T2) {                         // 800 of 512... (tid<800: covered by loop)
    }
    for (int cell = tid; cell < NT * T2; cell += BLK) {
        int t2 = cell % T2;
        int n  = cell / T2;
        size_t base = (size_t)(nbase + n) * K_ * T2 + t2;

        float2 v[K_];
        #pragma unroll
        for (int k = 0; k < K_; k++) v[k] = lam2[base + (size_t)k * T2];

        float mx = v[0].x, my = v[0].y;
        #pragma unroll
        for (int k = 1; k < K_; k++) { mx = fmaxf(mx, v[k].x); my = fmaxf(my, v[k].y); }

        float sx = 0.f, sy = 0.f;
        #pragma unroll
        for (int k = 0; k < K_; k++) {
            v[k].x = __expf(v[k].x - mx);
            v[k].y = __expf(v[k].y - my);
            sx += v[k].x; sy += v[k].y;
        }
        float ix = __fdividef(1.f, sx), iy = __fdividef(1.f, sy);

        #pragma unroll
        for (int k = 0; k < K_; k++) {
            float2 th; th.x = v[k].x * ix; th.y = v[k].y * iy;
            theta_s[(k * NT + n) * T2 + t2] = th;       // [k][n][t2]
            th2[base + (size_t)k * T2] = th;            // coalesced global write
        }
    }
    __syncthreads();

    // ---------------- Stage 2: two independent 256-thread halves ----------------
    // DUP-LANE MAPPING: warp = one n-group; t2c = lane % 25 (lanes 25-31 duplicate
    // lanes 0-6 -> broadcast-dedup in smem, benign duplicate pi stores).
    const int wid  = tid >> 5;            // 0..15
    const int lane = tid & 31;
    const int halfsel = wid >> 3;         // 0: warps 0-7, 1: warps 8-15
    const int ngrp    = wid & 7;
    const int n0      = ngrp * NNN;
    const int ltid    = tid & (HALF - 1);
    const int t2c     = (lane < T2) ? lane : lane - T2;

    float2* phi_s = phi_all + halfsel * (K_ * DC * PHIPAD);
    const int bar = 1 + halfsel;
    const int c_lo = halfsel ? 13 : 0;
    const int c_hi = halfsel ? NCHUNK : 13;

    for (int chunk = c_lo; chunk < c_hi; chunk++) {
        const int d0 = chunk * DC;

        // Stage phi chunk into padded layout [K_][DC][PHIPAD] (4000 float2, 16/thread)
        {
            const float2* src = pp2 + (size_t)d0 * T2;
            #pragma unroll 1
            for (int i = ltid; i < K_ * DC * T2; i += HALF) {
                int k   = i / (DC * T2);
                int rem = i - k * (DC * T2);
                int d   = rem / T2;
                int t2  = rem - d * T2;
                phi_s[(k * DC + d) * PHIPAD + t2] =
                    src[(size_t)k * (D_ * T2) + rem];
            }
        }
        half_bar(bar);

        // Compute (all 32 lanes; lanes 25-31 redundant with 0-6)
        {
            u64 acc[NNN][DC];
            #pragma unroll
            for (int i = 0; i < NNN; i++)
                #pragma unroll
                for (int d = 0; d < DC; d++) acc[i][d] = 0ull;

            #pragma unroll
            for (int k = 0; k < K_; k++) {
                u64 th[NNN], ph[DC];
                #pragma unroll
                for (int i = 0; i < NNN; i++)
                    th[i] = *(const u64*)&theta_s[(k * NT + n0 + i) * T2 + t2c];
                #pragma unroll
                for (int d = 0; d < DC; d++)
                    ph[d] = *(const u64*)&phi_s[(k * DC + d) * PHIPAD + t2c];
                #pragma unroll
                for (int i = 0; i < NNN; i++)
                    #pragma unroll
                    for (int d = 0; d < DC; d++)
                        acc[i][d] = ffma2(th[i], ph[d], acc[i][d]);
            }

            float2* pi_base = pi2 + ((size_t)(nbase + n0) * D_ + d0) * T2 + t2c;
            #pragma unroll
            for (int i = 0; i < NNN; i++) {
                #pragma unroll
                for (int d = 0; d < DC; d++) {
                    float2 f;
                    asm("mov.b64 {%0, %1}, %2;" : "=f"(f.x), "=f"(f.y) : "l"(acc[i][d]));
                    f.x = fminf(fmaxf(f.x, EPSF), 1.f - EPSF);
                    f.y = fminf(fmaxf(f.y, EPSF), 1.f - EPSF);
                    pi_base[((size_t)i * D_ + d) * T2] = f;
                }
            }
        }
        half_bar(bar);   // protect phi_s before next chunk's staging
    }
}

extern "C" void kernel_launch(void* const* d_in, const int* in_sizes, int n_in,
                              void* d_out, int out_size) {
    const float* lambda_ = (const float*)d_in[0];   // [N, K, T]
    const float* phi     = (const float*)d_in[1];   // [K, D, T]

    float* out         = (float*)d_out;
    float* pi_out      = out;                                // 200,000,000
    float* theta_out   = out + (size_t)N_ * D_ * T_;         //  20,000,000
    float* phiprob_out = theta_out + (size_t)N_ * K_ * T_;   //     200,000

    phi_sigmoid_kernel<<<(K_ * D_ * T_ + 255) / 256, 256>>>(phi, phiprob_out);

    size_t smem_bytes = sizeof(float2) *
        (size_t)(K_ * NT * T2 + 2 * K_ * DC * PHIPAD);       // 209920 B
    cudaFuncSetAttribute(main_kernel, cudaFuncAttributeMaxDynamicSharedMemorySize,
                         (int)smem_bytes);
    main_kernel<<<N_ / NT, BLK, smem_bytes>>>(lambda_, pi_out, theta_out);
}

// round 7
// speedup vs baseline: 1.9263x; 1.6204x over previous
#include <cuda_runtime.h>

// Problem dims
#define N_  20000
#define K_  20
#define T_  50
#define D_  200
#define T2  25            // t-pairs (f32x2 packing over fastest axis)
#define NT  32            // n rows per block
#define DC  10            // d chunk size (20 chunks, 10 per half)
#define NNN 4             // n rows per compute thread
#define GRP (NT/NNN)      // 8 groups
#define CTH (GRP*T2)      // 200 compute threads per half
#define HALF 224          // threads per d-half (7 warps; 6.25 busy in compute)
#define BLK  448          // 14 warps
#define NCHUNK (D_/DC)    // 20
#define EPSF 1e-8f

typedef unsigned long long u64;

// Precomputed sigmoid(phi); 16B-aligned for float4 staging loads.
__device__ __align__(16) float g_phiprob[K_ * D_ * T_];

__device__ __forceinline__ u64 ffma2(u64 a, u64 b, u64 c) {
    u64 d;
    asm("fma.rn.f32x2 %0, %1, %2, %3;" : "=l"(d) : "l"(a), "l"(b), "l"(c));
    return d;
}

__device__ __forceinline__ void half_bar(int bar_id) {
    asm volatile("bar.sync %0, %1;" :: "r"(bar_id), "r"(HALF) : "memory");
}

__global__ void phi_sigmoid_kernel(const float* __restrict__ phi,
                                   float* __restrict__ out_phi) {
    int i = blockIdx.x * blockDim.x + threadIdx.x;
    if (i < K_ * D_ * T_) {
        float p = __fdividef(1.f, 1.f + __expf(-phi[i]));
        out_phi[i]   = p;
        g_phiprob[i] = p;
    }
}

__global__ __launch_bounds__(BLK, 1) void main_kernel(
    const float* __restrict__ lambda_,
    float* __restrict__ pi_out,
    float* __restrict__ theta_out)
{
    extern __shared__ float2 smem[];
    float2* theta_s = smem;                      // [K_][NT][T2]      = 128000 B
    float2* phi_all = smem + K_ * NT * T2;       // 2 x [K_][DC][T2]  =  80000 B

    const int tid   = threadIdx.x;
    const int nbase = blockIdx.x * NT;
    const float2* lam2 = (const float2*)lambda_;
    float2*       th2  = (float2*)theta_out;
    float2*       pi2  = (float2*)pi_out;

    // ---------------- Stage 1: softmax over K for this block's 32 n's ----------------
    for (int cell = tid; cell < NT * T2; cell += BLK) {
        int t2 = cell % T2;
        int n  = cell / T2;
        size_t base = (size_t)(nbase + n) * K_ * T2 + t2;

        float2 v[K_];
        #pragma unroll
        for (int k = 0; k < K_; k++) v[k] = lam2[base + (size_t)k * T2];

        float mx = v[0].x, my = v[0].y;
        #pragma unroll
        for (int k = 1; k < K_; k++) { mx = fmaxf(mx, v[k].x); my = fmaxf(my, v[k].y); }

        float sx = 0.f, sy = 0.f;
        #pragma unroll
        for (int k = 0; k < K_; k++) {
            v[k].x = __expf(v[k].x - mx);
            v[k].y = __expf(v[k].y - my);
            sx += v[k].x; sy += v[k].y;
        }
        float ix = __fdividef(1.f, sx), iy = __fdividef(1.f, sy);

        #pragma unroll
        for (int k = 0; k < K_; k++) {
            float2 th; th.x = v[k].x * ix; th.y = v[k].y * iy;
            theta_s[(k * NT + n) * T2 + t2] = th;       // [k][n][t2]
            __stcs(&th2[base + (size_t)k * T2], th);    // streaming, write-once
        }
    }
    __syncthreads();

    // ---------------- Stage 2: two independent 224-thread halves ----------------
    // R2-style straddled mapping: compute thread = (n-group, t2) over CTH=200 of 224.
    const int halfsel = (tid >= HALF);
    const int ltid    = halfsel ? tid - HALF : tid;
    float2* phi_s = phi_all + halfsel * (K_ * DC * T2);
    const int bar = 1 + halfsel;
    const int c_lo = halfsel ? (NCHUNK / 2) : 0;
    const int c_hi = halfsel ? NCHUNK : (NCHUNK / 2);

    const int t2c = ltid % T2;
    const int g   = ltid / T2;              // 0..7 compute; g==8 (ltid 200..223) idle
    const int n0  = g * NNN;

    for (int chunk = c_lo; chunk < c_hi; chunk++) {
        const int d0 = chunk * DC;

        // Stage phi chunk [K_][DC][T2]: 2500 float4 (global rows contiguous per k)
        {
            const float4* src4 = (const float4*)g_phiprob + (size_t)d0 * T2 / 2;
            float4*       dst4 = (float4*)phi_s;
            #pragma unroll 1
            for (int i = ltid; i < K_ * DC * T2 / 2; i += HALF) {
                int k   = i / (DC * T2 / 2);
                int rem = i - k * (DC * T2 / 2);
                dst4[i] = src4[(size_t)k * (D_ * T2 / 2) + rem];
            }
        }
        half_bar(bar);

        if (ltid < CTH) {
            u64 acc[NNN][DC];
            #pragma unroll
            for (int i = 0; i < NNN; i++)
                #pragma unroll
                for (int d = 0; d < DC; d++) acc[i][d] = 0ull;

            #pragma unroll
            for (int k = 0; k < K_; k++) {
                u64 th[NNN], ph[DC];
                #pragma unroll
                for (int i = 0; i < NNN; i++)
                    th[i] = *(const u64*)&theta_s[(k * NT + n0 + i) * T2 + t2c];
                #pragma unroll
                for (int d = 0; d < DC; d++)
                    ph[d] = *(const u64*)&phi_s[(k * DC + d) * T2 + t2c];
                #pragma unroll
                for (int i = 0; i < NNN; i++)
                    #pragma unroll
                    for (int d = 0; d < DC; d++)
                        acc[i][d] = ffma2(th[i], ph[d], acc[i][d]);
            }

            float2* pi_base = pi2 + ((size_t)(nbase + n0) * D_ + d0) * T2 + t2c;
            #pragma unroll
            for (int i = 0; i < NNN; i++) {
                #pragma unroll
                for (int d = 0; d < DC; d++) {
                    float2 f;
                    asm("mov.b64 {%0, %1}, %2;" : "=f"(f.x), "=f"(f.y) : "l"(acc[i][d]));
                    f.x = fminf(fmaxf(f.x, EPSF), 1.f - EPSF);
                    f.y = fminf(fmaxf(f.y, EPSF), 1.f - EPSF);
                    __stcs(&pi_base[((size_t)i * D_ + d) * T2], f);   // streaming
                }
            }
        }
        half_bar(bar);   // protect phi_s before next chunk's staging
    }
}

extern "C" void kernel_launch(void* const* d_in, const int* in_sizes, int n_in,
                              void* d_out, int out_size) {
    const float* lambda_ = (const float*)d_in[0];   // [N, K, T]
    const float* phi     = (const float*)d_in[1];   // [K, D, T]

    float* out         = (float*)d_out;
    float* pi_out      = out;                                // 200,000,000
    float* theta_out   = out + (size_t)N_ * D_ * T_;         //  20,000,000
    float* phiprob_out = theta_out + (size_t)N_ * K_ * T_;   //     200,000

    phi_sigmoid_kernel<<<(K_ * D_ * T_ + 255) / 256, 256>>>(phi, phiprob_out);

    size_t smem_bytes = sizeof(float2) *
        (size_t)(K_ * NT * T2 + 2 * K_ * DC * T2);           // 208000 B
    cudaFuncSetAttribute(main_kernel, cudaFuncAttributeMaxDynamicSharedMemorySize,
                         (int)smem_bytes);
    main_kernel<<<N_ / NT, BLK, smem_bytes>>>(lambda_, pi_out, theta_out);
}